// round 3
// baseline (speedup 1.0000x reference)
#include <cuda_runtime.h>

// Problem constants (fixed by dataset: B=2, N=512, E=128, H=8, D=16)
#define B_    2
#define N_    512
#define E_    128
#define H_    8
#define D_    16
#define ROWS_ (B_ * N_)   // 1024

// Scratch (device globals: allocation-free rule)
__device__ float g_q[ROWS_ * E_];    // q * (1/sqrt(D)) * lrelu-split factors applied later
__device__ float g_v[ROWS_ * E_];

// ---------------- packed fp32x2 helpers (Blackwell FFMA2) -------------------
typedef unsigned long long u64;
#define ABS2_MASK 0x7fffffff7fffffffULL

__device__ __forceinline__ u64 pack2(float lo, float hi) {
    u64 r; asm("mov.b64 %0, {%1, %2};" : "=l"(r) : "f"(lo), "f"(hi)); return r;
}
__device__ __forceinline__ float2 unpk2(u64 v) {
    float2 f; asm("mov.b64 {%0, %1}, %2;" : "=f"(f.x), "=f"(f.y) : "l"(v)); return f;
}
__device__ __forceinline__ u64 ffma2(u64 a, u64 b, u64 c) {
    u64 d; asm("fma.rn.f32x2 %0, %1, %2, %3;" : "=l"(d) : "l"(a), "l"(b), "l"(c)); return d;
}

// ---------------------------------------------------------------------------
// qv GEMM: C[32r x 64c] = X[32 x 128] @ W[64 x 128]^T per CTA.
// 128 threads, 4 rows x 4 cols per thread (16 accumulators):
// per K-step-of-4: 4 x-LDS.128 + 4 w-LDS.128 feed 64 FFMA.
// smem: x_s[32][128] (16KB) + w_s[128][68] (34.8KB) = 50.8 KB (dynamic).
// ---------------------------------------------------------------------------
#define QV_SMEM_BYTES (32 * 128 * 4 + 128 * 68 * 4)

__global__ __launch_bounds__(128) void qv_kernel(const float* __restrict__ x,
                                                 const float* __restrict__ w_qkv) {
    extern __shared__ float sm[];
    float (*x_s)[128] = (float(*)[128])sm;
    float (*w_s)[68]  = (float(*)[68])(sm + 32 * 128);

    const int tid  = threadIdx.x;
    const int row0 = blockIdx.y * 32;
    const int st   = blockIdx.x;                           // 0,1 -> q ; 2,3 -> v
    const int wbase = (st < 2) ? st * 64 : 128 + st * 64;  // 0,64,256,320
    const float* w_rows = w_qkv + wbase * 128;

    // fill x: 1024 float4, coalesced
    {
        const float4* x4 = (const float4*)(x + row0 * 128);
        float4* xs4 = (float4*)x_s;
        #pragma unroll
        for (int i = 0; i < 8; i++) xs4[tid + i * 128] = x4[tid + i * 128];
    }
    // fill w transposed: 8192 scalars, gmem-coalesced over j
    #pragma unroll
    for (int i = 0; i < 64; i++) {
        int idx = tid + i * 128;          // 0..8191
        int j = idx & 127, c = idx >> 7;
        w_s[j][c] = w_rows[c * 128 + j];
    }
    __syncthreads();

    const int tx = tid & 15;              // col group: cols tx*4..+3
    const int ty = tid >> 4;              // row group: rows ty*4..+3
    float acc[4][4];
    #pragma unroll
    for (int r = 0; r < 4; r++)
        #pragma unroll
        for (int c = 0; c < 4; c++) acc[r][c] = 0.f;

    #pragma unroll 4
    for (int jb = 0; jb < 32; jb++) {
        float4 xr[4], wv[4];
        #pragma unroll
        for (int r = 0; r < 4; r++) xr[r] = *(const float4*)&x_s[ty * 4 + r][jb * 4];
        #pragma unroll
        for (int k = 0; k < 4; k++) wv[k] = *(const float4*)&w_s[jb * 4 + k][tx * 4];
        #pragma unroll
        for (int k = 0; k < 4; k++) {
            float xk[4] = {xr[0].x, xr[1].x, xr[2].x, xr[3].x};
            if (k == 1) { xk[0] = xr[0].y; xk[1] = xr[1].y; xk[2] = xr[2].y; xk[3] = xr[3].y; }
            if (k == 2) { xk[0] = xr[0].z; xk[1] = xr[1].z; xk[2] = xr[2].z; xk[3] = xr[3].z; }
            if (k == 3) { xk[0] = xr[0].w; xk[1] = xr[1].w; xk[2] = xr[2].w; xk[3] = xr[3].w; }
            #pragma unroll
            for (int r = 0; r < 4; r++) {
                acc[r][0] = fmaf(xk[r], wv[k].x, acc[r][0]);
                acc[r][1] = fmaf(xk[r], wv[k].y, acc[r][1]);
                acc[r][2] = fmaf(xk[r], wv[k].z, acc[r][2]);
                acc[r][3] = fmaf(xk[r], wv[k].w, acc[r][3]);
            }
        }
    }

    const float scale = (st < 2) ? 0.25f : 1.0f;
    float* dst = (st < 2) ? g_q : g_v;
    const int cg = (st & 1) * 64 + tx * 4;
    #pragma unroll
    for (int r = 0; r < 4; r++) {
        float4 o = {acc[r][0] * scale, acc[r][1] * scale, acc[r][2] * scale, acc[r][3] * scale};
        *(float4*)&dst[(row0 + ty * 4 + r) * 128 + cg] = o;
    }
}

// ---------------------------------------------------------------------------
// Fused attention + output projection. One CTA per (b,n) row, one warp per
// head, 16 m per lane, packed f32x2 over d-pairs.
//   lrelu(t) = 0.505*t + 0.495*|t|
// Final per-head d-reduction: 16-shuffle butterfly transpose-reduce
// (lane L ends with d = bitrev4(L&15), full 32-lane sum).
// Then: out[row] = hat @ w_prj^T + b_prj, with w_prj staged in smem (direct
// copy, lane-skewed j iteration keeps reads conflict-free).
// ---------------------------------------------------------------------------
// dynamic smem layout (floats):
//   w_s:     [0, 16384)        w_prj direct copy [c][j]
//   e_s:     [16384, 16896)
//   q_s:     [16896, 17024)
//   v_s:     [17024, 17152)
//   wk_s:    [17152, 17280)
//   bk_s:    [17280, 17408)
//   wv_s:    [17408, 17536)
//   bv_s:    [17536, 17664)
//   hat_s:   [17664, 17792)
//   partial: [17792, 18048)
#define AT_SMEM_FLOATS 18048
#define AT_SMEM_BYTES  (AT_SMEM_FLOATS * 4)

__global__ __launch_bounds__(256) void attn_proj_kernel(const float* __restrict__ e,
                                                        const float* __restrict__ w_ekv,
                                                        const float* __restrict__ b_ekv,
                                                        const float* __restrict__ w_prj,
                                                        const float* __restrict__ b_prj,
                                                        float* __restrict__ out) {
    extern __shared__ float sm[];
    float* w_s     = sm;
    float* e_s     = sm + 16384;
    float* q_s     = sm + 16896;
    float* v_s     = sm + 17024;
    float* wk_s    = sm + 17152;
    float* bk_s    = sm + 17280;
    float* wv_s    = sm + 17408;
    float* bv_s    = sm + 17536;
    float* hat_s   = sm + 17664;
    float* partial = sm + 17792;

    const int row  = blockIdx.x;     // b*N + n
    const int tid  = threadIdx.x;
    const int lane = tid & 31;
    const int h    = tid >> 5;       // warp == head

    // stage w_prj: 4096 float4, coalesced direct copy
    {
        const float4* w4 = (const float4*)w_prj;
        float4* ws4 = (float4*)w_s;
        #pragma unroll
        for (int i = 0; i < 16; i++) ws4[tid + i * 256] = w4[tid + i * 256];
    }
    for (int idx = tid; idx < N_; idx += 256) e_s[idx] = e[row * N_ + idx];
    if (tid < 128) {
        q_s[tid]  = g_q[row * 128 + tid];
        v_s[tid]  = g_v[row * 128 + tid];
        wk_s[tid] = w_ekv[tid];
        bk_s[tid] = b_ekv[tid];
    } else {
        int t = tid - 128;
        wv_s[t] = w_ekv[128 + t];
        bv_s[t] = b_ekv[128 + t];
    }
    __syncthreads();

    // ---- phase 1: scores ----
    u64 wk2[8], bk2[8], qa2[8], qb2[8];
    #pragma unroll
    for (int dd = 0; dd < 8; dd++) {
        float2 w = ((const float2*)wk_s)[h * 8 + dd];
        float2 b = ((const float2*)bk_s)[h * 8 + dd];
        float2 q = ((const float2*)q_s)[h * 8 + dd];
        wk2[dd] = pack2(w.x, w.y);
        bk2[dd] = pack2(b.x, b.y);
        qa2[dd] = pack2(0.505f * q.x, 0.505f * q.y);
        qb2[dd] = pack2(0.495f * q.x, 0.495f * q.y);
    }
    float ev[16], s[16];
    #pragma unroll
    for (int i = 0; i < 16; i++) {
        const float em = e_s[i * 32 + lane];
        ev[i] = em;
        const u64 em2 = pack2(em, em);
        u64 acc2 = 0ULL;
        #pragma unroll
        for (int dd = 0; dd < 8; dd++) {
            u64 t2 = ffma2(em2, wk2[dd], bk2[dd]);
            u64 a2 = t2 & ABS2_MASK;            // |t| per half (alu pipe)
            acc2 = ffma2(qa2[dd], t2, acc2);
            acc2 = ffma2(qb2[dd], a2, acc2);
        }
        float2 f = unpk2(acc2);
        s[i] = f.x + f.y;
    }

    // ---- softmax over m ----
    float mx = s[0];
    #pragma unroll
    for (int i = 1; i < 16; i++) mx = fmaxf(mx, s[i]);
    #pragma unroll
    for (int k = 16; k >= 1; k >>= 1) mx = fmaxf(mx, __shfl_xor_sync(0xffffffffu, mx, k));
    float Z = 0.f;
    #pragma unroll
    for (int i = 0; i < 16; i++) { s[i] = __expf(s[i] - mx); Z += s[i]; }
    #pragma unroll
    for (int k = 16; k >= 1; k >>= 1) Z += __shfl_xor_sync(0xffffffffu, Z, k);
    const float invZ = 1.f / Z;

    // ---- phase 2: V accumulation ----
    u64 wv2[8], bv2[8], A2[8], B2[8];
    #pragma unroll
    for (int dd = 0; dd < 8; dd++) {
        float2 w = ((const float2*)wv_s)[h * 8 + dd];
        float2 b = ((const float2*)bv_s)[h * 8 + dd];
        wv2[dd] = pack2(w.x, w.y);
        bv2[dd] = pack2(b.x, b.y);
        A2[dd] = 0ULL;
        B2[dd] = 0ULL;
    }
    #pragma unroll
    for (int i = 0; i < 16; i++) {
        const u64 em2 = pack2(ev[i], ev[i]);
        const u64 p2  = pack2(s[i], s[i]);
        #pragma unroll
        for (int dd = 0; dd < 8; dd++) {
            u64 t2 = ffma2(em2, wv2[dd], bv2[dd]);
            u64 a2 = t2 & ABS2_MASK;
            A2[dd] = ffma2(p2, t2, A2[dd]);
            B2[dd] = ffma2(p2, a2, B2[dd]);
        }
    }
    float acc[16];
    #pragma unroll
    for (int dd = 0; dd < 8; dd++) {
        float2 fa = unpk2(A2[dd]);
        float2 fb = unpk2(B2[dd]);
        acc[2 * dd]     = 0.505f * fa.x + 0.495f * fb.x;
        acc[2 * dd + 1] = 0.505f * fa.y + 0.495f * fb.y;
    }

    // ---- butterfly transpose-reduce: 16 shuffles total ----
    // round r (r=0..3): keep the half selected by lane bit r, exchange the other
    #pragma unroll
    for (int r = 0; r < 4; r++) {
        const int half = 8 >> r;
        const bool hi = (lane >> r) & 1;
        #pragma unroll
        for (int j = 0; j < 8; j++) {
            if (j < half) {
                float send = hi ? acc[j] : acc[j + half];
                float keep = hi ? acc[j + half] : acc[j];
                float recv = __shfl_xor_sync(0xffffffffu, send, 1 << r);
                acc[j] = keep + recv;
            }
        }
    }
    float tot = acc[0] + __shfl_xor_sync(0xffffffffu, acc[0], 16);
    // lane L holds d = bitrev4(L&15)
    if (lane < 16) {
        int d = ((lane & 1) << 3) | (((lane >> 1) & 1) << 2)
              | (((lane >> 2) & 1) << 1) | ((lane >> 3) & 1);
        hat_s[h * 16 + d] = v_s[h * 16 + d] + tot * invZ;
    }
    __syncthreads();

    // ---- fused projection: out[c] = b_prj[c] + sum_j hat[j] * w_prj[c][j] ----
    {
        const int c  = tid & 127;
        const int jh = tid >> 7;          // 0/1: j-halves [0,64) / [64,128)
        const int base = jh * 64;
        const int skew = tid & 63;        // lane-skewed start -> conflict-free
        float a0 = 0.f, a1 = 0.f;
        #pragma unroll 8
        for (int jj = 0; jj < 64; jj += 2) {
            int j0 = base + ((skew + jj) & 63);
            int j1 = base + ((skew + jj + 1) & 63);
            a0 = fmaf(hat_s[j0], w_s[c * 128 + j0], a0);
            a1 = fmaf(hat_s[j1], w_s[c * 128 + j1], a1);
        }
        partial[tid] = a0 + a1;
    }
    __syncthreads();
    if (tid < 128)
        out[row * 128 + tid] = partial[tid] + partial[tid + 128] + b_prj[tid];
}

// ---------------------------------------------------------------------------
extern "C" void kernel_launch(void* const* d_in, const int* in_sizes, int n_in,
                              void* d_out, int out_size) {
    const float* x     = (const float*)d_in[0];
    const float* e     = (const float*)d_in[1];
    const float* w_qkv = (const float*)d_in[2];
    const float* w_ekv = (const float*)d_in[3];
    const float* b_ekv = (const float*)d_in[4];
    const float* w_prj = (const float*)d_in[5];
    const float* b_prj = (const float*)d_in[6];
    float* out = (float*)d_out;

    cudaFuncSetAttribute((const void*)qv_kernel,
                         cudaFuncAttributeMaxDynamicSharedMemorySize, QV_SMEM_BYTES);
    cudaFuncSetAttribute((const void*)attn_proj_kernel,
                         cudaFuncAttributeMaxDynamicSharedMemorySize, AT_SMEM_BYTES);

    qv_kernel       <<<dim3(4, 32), 128, QV_SMEM_BYTES>>>(x, w_qkv);
    attn_proj_kernel<<<ROWS_,       256, AT_SMEM_BYTES>>>(e, w_ekv, b_ekv, w_prj, b_prj, out);
}

// round 4
// speedup vs baseline: 1.2031x; 1.2031x over previous
#include <cuda_runtime.h>

// Problem constants (fixed by dataset: B=2, N=512, E=128, H=8, D=16)
#define B_    2
#define N_    512
#define E_    128
#define H_    8
#define D_    16
#define ROWS_ (B_ * N_)   // 1024

// Scratch (device globals: allocation-free rule)
__device__ float g_q[ROWS_ * E_];    // q * 0.25 (1/sqrt(D))
__device__ float g_v[ROWS_ * E_];

// ---------------- packed fp32x2 helpers (Blackwell FFMA2) -------------------
typedef unsigned long long u64;
#define ABS2_MASK 0x7fffffff7fffffffULL

__device__ __forceinline__ u64 pack2(float lo, float hi) {
    u64 r; asm("mov.b64 %0, {%1, %2};" : "=l"(r) : "f"(lo), "f"(hi)); return r;
}
__device__ __forceinline__ float2 unpk2(u64 v) {
    float2 f; asm("mov.b64 {%0, %1}, %2;" : "=f"(f.x), "=f"(f.y) : "l"(v)); return f;
}
__device__ __forceinline__ u64 ffma2(u64 a, u64 b, u64 c) {
    u64 d; asm("fma.rn.f32x2 %0, %1, %2, %3;" : "=l"(d) : "l"(a), "l"(b), "l"(c)); return d;
}

// ---------------------------------------------------------------------------
// qv GEMM: C[32r x 64c] = X[32 x 128] @ W[64 x 128]^T per CTA. (unchanged;
// measured ~3.7us) 128 threads, 4x4 register blocking.
// ---------------------------------------------------------------------------
#define QV_SMEM_BYTES (32 * 128 * 4 + 128 * 68 * 4)

__global__ __launch_bounds__(128) void qv_kernel(const float* __restrict__ x,
                                                 const float* __restrict__ w_qkv) {
    extern __shared__ float sm[];
    float (*x_s)[128] = (float(*)[128])sm;
    float (*w_s)[68]  = (float(*)[68])(sm + 32 * 128);

    const int tid  = threadIdx.x;
    const int row0 = blockIdx.y * 32;
    const int st   = blockIdx.x;                           // 0,1 -> q ; 2,3 -> v
    const int wbase = (st < 2) ? st * 64 : 128 + st * 64;  // 0,64,256,320
    const float* w_rows = w_qkv + wbase * 128;

    {
        const float4* x4 = (const float4*)(x + row0 * 128);
        float4* xs4 = (float4*)x_s;
        #pragma unroll
        for (int i = 0; i < 8; i++) xs4[tid + i * 128] = x4[tid + i * 128];
    }
    #pragma unroll
    for (int i = 0; i < 64; i++) {
        int idx = tid + i * 128;
        int j = idx & 127, c = idx >> 7;
        w_s[j][c] = w_rows[c * 128 + j];
    }
    __syncthreads();

    const int tx = tid & 15;
    const int ty = tid >> 4;
    float acc[4][4];
    #pragma unroll
    for (int r = 0; r < 4; r++)
        #pragma unroll
        for (int c = 0; c < 4; c++) acc[r][c] = 0.f;

    #pragma unroll 4
    for (int jb = 0; jb < 32; jb++) {
        float4 xr[4], wv[4];
        #pragma unroll
        for (int r = 0; r < 4; r++) xr[r] = *(const float4*)&x_s[ty * 4 + r][jb * 4];
        #pragma unroll
        for (int k = 0; k < 4; k++) wv[k] = *(const float4*)&w_s[jb * 4 + k][tx * 4];
        #pragma unroll
        for (int k = 0; k < 4; k++) {
            float xk[4] = {xr[0].x, xr[1].x, xr[2].x, xr[3].x};
            if (k == 1) { xk[0] = xr[0].y; xk[1] = xr[1].y; xk[2] = xr[2].y; xk[3] = xr[3].y; }
            if (k == 2) { xk[0] = xr[0].z; xk[1] = xr[1].z; xk[2] = xr[2].z; xk[3] = xr[3].z; }
            if (k == 3) { xk[0] = xr[0].w; xk[1] = xr[1].w; xk[2] = xr[2].w; xk[3] = xr[3].w; }
            #pragma unroll
            for (int r = 0; r < 4; r++) {
                acc[r][0] = fmaf(xk[r], wv[k].x, acc[r][0]);
                acc[r][1] = fmaf(xk[r], wv[k].y, acc[r][1]);
                acc[r][2] = fmaf(xk[r], wv[k].z, acc[r][2]);
                acc[r][3] = fmaf(xk[r], wv[k].w, acc[r][3]);
            }
        }
    }

    const float scale = (st < 2) ? 0.25f : 1.0f;
    float* dst = (st < 2) ? g_q : g_v;
    const int cg = (st & 1) * 64 + tx * 4;
    #pragma unroll
    for (int r = 0; r < 4; r++) {
        float4 o = {acc[r][0] * scale, acc[r][1] * scale, acc[r][2] * scale, acc[r][3] * scale};
        *(float4*)&dst[(row0 + ty * 4 + r) * 128 + cg] = o;
    }
}

// ---------------------------------------------------------------------------
// Fused attention + projection. One CTA per (b,n), one warp per head, 16 m
// per lane, packed f32x2 over d-pairs.
//
// lrelu(t) = 0.505 t + 0.495 |t|; the linear part folds out of both loops:
//   s[m]   = c0 + c1*em + sum_d (0.495 q_d)|em*wk_d + bk_d|
//   hat_d  = v_d + [0.505(wv_d*S1 + bv_d*Z) + 0.495*sum_m p|em*wv_d+bv_d|]/Z
// with c1 = 0.505 sum q wk, c0 = 0.505 sum q bk, S1 = sum_m p*em.
// Inner loops: 2 FFMA2 + 1 LOP3.64 per packed pair.
// Projection: warp-per-16-cols GEMV, w_prj via LDG (L1-resident), shfl reduce.
// ---------------------------------------------------------------------------
__global__ __launch_bounds__(256, 2) void attn_proj_kernel(const float* __restrict__ e,
                                                           const float* __restrict__ w_ekv,
                                                           const float* __restrict__ b_ekv,
                                                           const float* __restrict__ w_prj,
                                                           const float* __restrict__ b_prj,
                                                           float* __restrict__ out) {
    __shared__ float e_s[N_];
    __shared__ float q_s[128], v_s[128];
    __shared__ float wk_s[128], bk_s[128], wv_s[128], bv_s[128];
    __shared__ float hat_s[128];

    const int row  = blockIdx.x;     // b*N + n
    const int tid  = threadIdx.x;
    const int lane = tid & 31;
    const int h    = tid >> 5;       // warp == head

    for (int idx = tid; idx < N_; idx += 256) e_s[idx] = e[row * N_ + idx];
    if (tid < 128) {
        q_s[tid]  = g_q[row * 128 + tid];
        v_s[tid]  = g_v[row * 128 + tid];
        wk_s[tid] = w_ekv[tid];
        bk_s[tid] = b_ekv[tid];
    } else {
        int t = tid - 128;
        wv_s[t] = w_ekv[128 + t];
        bv_s[t] = b_ekv[128 + t];
    }
    __syncthreads();

    // ---- per-head constants + packed K params ----
    u64 wk2[8], bk2[8], qb2[8];
    float c0 = 0.f, c1 = 0.f;
    #pragma unroll
    for (int dd = 0; dd < 8; dd++) {
        float2 w = ((const float2*)wk_s)[h * 8 + dd];
        float2 b = ((const float2*)bk_s)[h * 8 + dd];
        float2 q = ((const float2*)q_s)[h * 8 + dd];
        wk2[dd] = pack2(w.x, w.y);
        bk2[dd] = pack2(b.x, b.y);
        qb2[dd] = pack2(0.495f * q.x, 0.495f * q.y);
        c1 = fmaf(q.x, w.x, fmaf(q.y, w.y, c1));
        c0 = fmaf(q.x, b.x, fmaf(q.y, b.y, c0));
    }
    c1 *= 0.505f; c0 *= 0.505f;

    // ---- phase 1: scores ----
    float ev[16], s[16];
    #pragma unroll
    for (int i = 0; i < 16; i++) {
        const float em = e_s[i * 32 + lane];
        ev[i] = em;
        const u64 em2 = pack2(em, em);
        u64 acc2 = 0ULL;
        #pragma unroll
        for (int dd = 0; dd < 8; dd++) {
            u64 t2 = ffma2(em2, wk2[dd], bk2[dd]);
            acc2 = ffma2(qb2[dd], t2 & ABS2_MASK, acc2);
        }
        float2 f = unpk2(acc2);
        s[i] = fmaf(c1, em, c0) + f.x + f.y;
    }

    // ---- softmax over m (+ S1 = sum p*em) ----
    float mx = s[0];
    #pragma unroll
    for (int i = 1; i < 16; i++) mx = fmaxf(mx, s[i]);
    #pragma unroll
    for (int k = 16; k >= 1; k >>= 1) mx = fmaxf(mx, __shfl_xor_sync(0xffffffffu, mx, k));
    float Z = 0.f, S1 = 0.f;
    #pragma unroll
    for (int i = 0; i < 16; i++) {
        s[i] = __expf(s[i] - mx);
        Z += s[i];
        S1 = fmaf(s[i], ev[i], S1);
    }
    #pragma unroll
    for (int k = 16; k >= 1; k >>= 1) {
        Z  += __shfl_xor_sync(0xffffffffu, Z, k);
        S1 += __shfl_xor_sync(0xffffffffu, S1, k);
    }
    const float invZ = 1.f / Z;

    // ---- phase 2: abs-term accumulation only ----
    u64 wv2[8], bv2[8], B2[8];
    #pragma unroll
    for (int dd = 0; dd < 8; dd++) {
        float2 w = ((const float2*)wv_s)[h * 8 + dd];
        float2 b = ((const float2*)bv_s)[h * 8 + dd];
        wv2[dd] = pack2(w.x, w.y);
        bv2[dd] = pack2(b.x, b.y);
        B2[dd] = 0ULL;
    }
    #pragma unroll
    for (int i = 0; i < 16; i++) {
        const u64 em2 = pack2(ev[i], ev[i]);
        const u64 p2  = pack2(s[i], s[i]);
        #pragma unroll
        for (int dd = 0; dd < 8; dd++) {
            u64 t2 = ffma2(em2, wv2[dd], bv2[dd]);
            B2[dd] = ffma2(p2, t2 & ABS2_MASK, B2[dd]);
        }
    }
    float acc[16];
    #pragma unroll
    for (int dd = 0; dd < 8; dd++) {
        float2 fb = unpk2(B2[dd]);
        acc[2 * dd]     = fb.x;
        acc[2 * dd + 1] = fb.y;
    }

    // ---- butterfly transpose-reduce: 16 shuffles (lane L -> d=bitrev4(L)) ----
    #pragma unroll
    for (int r = 0; r < 4; r++) {
        const int half = 8 >> r;
        const bool hi = (lane >> r) & 1;
        #pragma unroll
        for (int j = 0; j < 8; j++) {
            if (j < half) {
                float send = hi ? acc[j] : acc[j + half];
                float keep = hi ? acc[j + half] : acc[j];
                float recv = __shfl_xor_sync(0xffffffffu, send, 1 << r);
                acc[j] = keep + recv;
            }
        }
    }
    float tot = acc[0] + __shfl_xor_sync(0xffffffffu, acc[0], 16);
    if (lane < 16) {
        int d = ((lane & 1) << 3) | (((lane >> 1) & 1) << 2)
              | (((lane >> 2) & 1) << 1) | ((lane >> 3) & 1);
        float wvd = wv_s[h * 16 + d], bvd = bv_s[h * 16 + d];
        float lin = 0.505f * fmaf(wvd, S1, bvd * Z);
        hat_s[h * 16 + d] = v_s[h * 16 + d] + fmaf(0.495f, tot, lin) * invZ;
    }
    __syncthreads();

    // ---- fused projection: warp w -> cols [w*16, w*16+16) ----
    {
        float4 h4 = ((const float4*)hat_s)[lane];   // hat[lane*4 .. +3]
        #pragma unroll
        for (int i = 0; i < 16; i++) {
            const int c = h * 16 + i;
            float4 wv = *(const float4*)&w_prj[c * 128 + lane * 4];
            float a = fmaf(h4.x, wv.x, fmaf(h4.y, wv.y, fmaf(h4.z, wv.z, h4.w * wv.w)));
            #pragma unroll
            for (int k = 16; k >= 1; k >>= 1) a += __shfl_xor_sync(0xffffffffu, a, k);
            if (lane == i) out[row * 128 + c] = a + b_prj[c];
        }
    }
}

// ---------------------------------------------------------------------------
extern "C" void kernel_launch(void* const* d_in, const int* in_sizes, int n_in,
                              void* d_out, int out_size) {
    const float* x     = (const float*)d_in[0];
    const float* e     = (const float*)d_in[1];
    const float* w_qkv = (const float*)d_in[2];
    const float* w_ekv = (const float*)d_in[3];
    const float* b_ekv = (const float*)d_in[4];
    const float* w_prj = (const float*)d_in[5];
    const float* b_prj = (const float*)d_in[6];
    float* out = (float*)d_out;

    cudaFuncSetAttribute((const void*)qv_kernel,
                         cudaFuncAttributeMaxDynamicSharedMemorySize, QV_SMEM_BYTES);

    qv_kernel       <<<dim3(4, 32), 128, QV_SMEM_BYTES>>>(x, w_qkv);
    attn_proj_kernel<<<ROWS_,       256>>>(e, w_ekv, b_ekv, w_prj, b_prj, out);
}

// round 5
// speedup vs baseline: 1.3778x; 1.1452x over previous
#include <cuda_runtime.h>

// Problem constants (fixed by dataset: B=2, N=512, E=128, H=8, D=16)
#define B_    2
#define N_    512
#define E_    128
#define H_    8
#define D_    16
#define ROWS_ (B_ * N_)   // 1024

// Scratch (device globals: allocation-free rule)
__device__ float g_q[ROWS_ * E_];    // q * 0.25 (1/sqrt(D))
__device__ float g_v[ROWS_ * E_];

// ---------------- packed fp32x2 helpers (Blackwell FFMA2/FADD2) -------------
typedef unsigned long long u64;
#define ABS2_MASK 0x7fffffff7fffffffULL

__device__ __forceinline__ u64 pack2(float lo, float hi) {
    u64 r; asm("mov.b64 %0, {%1, %2};" : "=l"(r) : "f"(lo), "f"(hi)); return r;
}
__device__ __forceinline__ float2 unpk2(u64 v) {
    float2 f; asm("mov.b64 {%0, %1}, %2;" : "=f"(f.x), "=f"(f.y) : "l"(v)); return f;
}
__device__ __forceinline__ u64 ffma2(u64 a, u64 b, u64 c) {
    u64 d; asm("fma.rn.f32x2 %0, %1, %2, %3;" : "=l"(d) : "l"(a), "l"(b), "l"(c)); return d;
}
__device__ __forceinline__ u64 fadd2(u64 a, u64 b) {
    u64 d; asm("add.rn.f32x2 %0, %1, %2;" : "=l"(d) : "l"(a), "l"(b)); return d;
}

// ---------------------------------------------------------------------------
// qv GEMM: C[32r x 64c] = X[32 x 128] @ W[64 x 128]^T per CTA (measured 3.7us)
// ---------------------------------------------------------------------------
#define QV_SMEM_BYTES (32 * 128 * 4 + 128 * 68 * 4)

__global__ __launch_bounds__(128) void qv_kernel(const float* __restrict__ x,
                                                 const float* __restrict__ w_qkv) {
    extern __shared__ float sm[];
    float (*x_s)[128] = (float(*)[128])sm;
    float (*w_s)[68]  = (float(*)[68])(sm + 32 * 128);

    const int tid  = threadIdx.x;
    const int row0 = blockIdx.y * 32;
    const int st   = blockIdx.x;                           // 0,1 -> q ; 2,3 -> v
    const int wbase = (st < 2) ? st * 64 : 128 + st * 64;  // 0,64,256,320
    const float* w_rows = w_qkv + wbase * 128;

    {
        const float4* x4 = (const float4*)(x + row0 * 128);
        float4* xs4 = (float4*)x_s;
        #pragma unroll
        for (int i = 0; i < 8; i++) xs4[tid + i * 128] = x4[tid + i * 128];
    }
    #pragma unroll
    for (int i = 0; i < 64; i++) {
        int idx = tid + i * 128;
        int j = idx & 127, c = idx >> 7;
        w_s[j][c] = w_rows[c * 128 + j];
    }
    __syncthreads();

    const int tx = tid & 15;
    const int ty = tid >> 4;
    float acc[4][4];
    #pragma unroll
    for (int r = 0; r < 4; r++)
        #pragma unroll
        for (int c = 0; c < 4; c++) acc[r][c] = 0.f;

    #pragma unroll 4
    for (int jb = 0; jb < 32; jb++) {
        float4 xr[4], wv[4];
        #pragma unroll
        for (int r = 0; r < 4; r++) xr[r] = *(const float4*)&x_s[ty * 4 + r][jb * 4];
        #pragma unroll
        for (int k = 0; k < 4; k++) wv[k] = *(const float4*)&w_s[jb * 4 + k][tx * 4];
        #pragma unroll
        for (int k = 0; k < 4; k++) {
            float xk[4] = {xr[0].x, xr[1].x, xr[2].x, xr[3].x};
            if (k == 1) { xk[0] = xr[0].y; xk[1] = xr[1].y; xk[2] = xr[2].y; xk[3] = xr[3].y; }
            if (k == 2) { xk[0] = xr[0].z; xk[1] = xr[1].z; xk[2] = xr[2].z; xk[3] = xr[3].z; }
            if (k == 3) { xk[0] = xr[0].w; xk[1] = xr[1].w; xk[2] = xr[2].w; xk[3] = xr[3].w; }
            #pragma unroll
            for (int r = 0; r < 4; r++) {
                acc[r][0] = fmaf(xk[r], wv[k].x, acc[r][0]);
                acc[r][1] = fmaf(xk[r], wv[k].y, acc[r][1]);
                acc[r][2] = fmaf(xk[r], wv[k].z, acc[r][2]);
                acc[r][3] = fmaf(xk[r], wv[k].w, acc[r][3]);
            }
        }
    }

    const float scale = (st < 2) ? 0.25f : 1.0f;
    float* dst = (st < 2) ? g_q : g_v;
    const int cg = (st & 1) * 64 + tx * 4;
    #pragma unroll
    for (int r = 0; r < 4; r++) {
        float4 o = {acc[r][0] * scale, acc[r][1] * scale, acc[r][2] * scale, acc[r][3] * scale};
        *(float4*)&dst[(row0 + ty * 4 + r) * 128 + cg] = o;
    }
}

// ---------------------------------------------------------------------------
// Fused attention + projection. One CTA per (b,n), warp = head, 16 m per lane.
//
// Reparam:  lrelu(em*w + b) = 0.505(em*w + b) + 0.495|w|*|em + b/w|
//   s[m]   = c0 + c1*em + sum_d g_d |em + r_d|          (g=0.495 q|wk|, r=bk/wk)
//   hat_d  = v_d + [0.505(wv_d*S1 + bv_d*Z) + 0.495|wv_d| * sum_m p|em + rv_d|]/Z
// Inner loops: ADD2 + 2xLOP(abs) + FFMA2 per packed d-pair (2 issues/element,
// balanced across fma/alu pipes). Only 32 param regs live per phase ->
// 3 CTAs/SM occupancy.
// ---------------------------------------------------------------------------
__global__ __launch_bounds__(256, 3) void attn_proj_kernel(const float* __restrict__ e,
                                                           const float* __restrict__ w_ekv,
                                                           const float* __restrict__ b_ekv,
                                                           const float* __restrict__ w_prj,
                                                           const float* __restrict__ b_prj,
                                                           float* __restrict__ out) {
    __shared__ float e_s[N_];
    __shared__ float q_s[128], v_s[128];
    __shared__ float wk_s[128], bk_s[128], wv_s[128], bv_s[128];
    __shared__ float hat_s[128];

    const int row  = blockIdx.x;     // b*N + n
    const int tid  = threadIdx.x;
    const int lane = tid & 31;
    const int h    = tid >> 5;       // warp == head

    if (tid < 128)
        ((float4*)e_s)[tid] = ((const float4*)(e + row * N_))[tid];
    if (tid < 128) {
        q_s[tid]  = g_q[row * 128 + tid];
        v_s[tid]  = g_v[row * 128 + tid];
        wk_s[tid] = w_ekv[tid];
        bk_s[tid] = b_ekv[tid];
    } else {
        int t = tid - 128;
        wv_s[t] = w_ekv[128 + t];
        bv_s[t] = b_ekv[128 + t];
    }
    __syncthreads();

    float s[16];

    // ======== phase 1: scores ========
    {
        u64 r2[8], g2[8];
        float c0 = 0.f, c1 = 0.f;
        #pragma unroll
        for (int dd = 0; dd < 8; dd++) {
            float2 w = ((const float2*)wk_s)[h * 8 + dd];
            float2 b = ((const float2*)bk_s)[h * 8 + dd];
            float2 q = ((const float2*)q_s)[h * 8 + dd];
            r2[dd] = pack2(__fdividef(b.x, w.x), __fdividef(b.y, w.y));
            g2[dd] = pack2(0.495f * q.x * fabsf(w.x), 0.495f * q.y * fabsf(w.y));
            c1 = fmaf(q.x, w.x, fmaf(q.y, w.y, c1));
            c0 = fmaf(q.x, b.x, fmaf(q.y, b.y, c0));
        }
        c1 *= 0.505f; c0 *= 0.505f;

        #pragma unroll
        for (int i = 0; i < 16; i++) {
            const float em = e_s[i * 32 + lane];
            const u64 em2 = pack2(em, em);
            u64 acc2 = 0ULL;
            #pragma unroll
            for (int dd = 0; dd < 8; dd++) {
                u64 u2 = fadd2(em2, r2[dd]);
                acc2 = ffma2(g2[dd], u2 & ABS2_MASK, acc2);
            }
            float2 f = unpk2(acc2);
            s[i] = fmaf(c1, em, c0) + f.x + f.y;
        }
    }

    // ======== softmax over m (+ S1 = sum p*em) ========
    float mx = s[0];
    #pragma unroll
    for (int i = 1; i < 16; i++) mx = fmaxf(mx, s[i]);
    #pragma unroll
    for (int k = 16; k >= 1; k >>= 1) mx = fmaxf(mx, __shfl_xor_sync(0xffffffffu, mx, k));
    float Z = 0.f, S1 = 0.f;
    #pragma unroll
    for (int i = 0; i < 16; i++) {
        s[i] = __expf(s[i] - mx);
        Z += s[i];
        S1 = fmaf(s[i], e_s[i * 32 + lane], S1);
    }
    #pragma unroll
    for (int k = 16; k >= 1; k >>= 1) {
        Z  += __shfl_xor_sync(0xffffffffu, Z, k);
        S1 += __shfl_xor_sync(0xffffffffu, S1, k);
    }
    const float invZ = 1.f / Z;

    // ======== phase 2: acc_d = sum_m p |em + bv_d/wv_d| ========
    float acc[16];
    {
        u64 rv2[8], acc2[8];
        #pragma unroll
        for (int dd = 0; dd < 8; dd++) {
            float2 w = ((const float2*)wv_s)[h * 8 + dd];
            float2 b = ((const float2*)bv_s)[h * 8 + dd];
            rv2[dd] = pack2(__fdividef(b.x, w.x), __fdividef(b.y, w.y));
            acc2[dd] = 0ULL;
        }
        #pragma unroll
        for (int i = 0; i < 16; i++) {
            const float em = e_s[i * 32 + lane];
            const u64 em2 = pack2(em, em);
            const u64 p2  = pack2(s[i], s[i]);
            #pragma unroll
            for (int dd = 0; dd < 8; dd++) {
                u64 u2 = fadd2(em2, rv2[dd]);
                acc2[dd] = ffma2(p2, u2 & ABS2_MASK, acc2[dd]);
            }
        }
        #pragma unroll
        for (int dd = 0; dd < 8; dd++) {
            float2 fb = unpk2(acc2[dd]);
            acc[2 * dd]     = fb.x;
            acc[2 * dd + 1] = fb.y;
        }
    }

    // ---- butterfly transpose-reduce: lane L ends with d = bitrev4(L&15) ----
    #pragma unroll
    for (int r = 0; r < 4; r++) {
        const int half = 8 >> r;
        const bool hi = (lane >> r) & 1;
        #pragma unroll
        for (int j = 0; j < 8; j++) {
            if (j < half) {
                float send = hi ? acc[j] : acc[j + half];
                float keep = hi ? acc[j + half] : acc[j];
                float recv = __shfl_xor_sync(0xffffffffu, send, 1 << r);
                acc[j] = keep + recv;
            }
        }
    }
    float tot = acc[0] + __shfl_xor_sync(0xffffffffu, acc[0], 16);
    if (lane < 16) {
        int d = ((lane & 1) << 3) | (((lane >> 1) & 1) << 2)
              | (((lane >> 2) & 1) << 1) | ((lane >> 3) & 1);
        float wvd = wv_s[h * 16 + d], bvd = bv_s[h * 16 + d];
        float lin = 0.505f * fmaf(wvd, S1, bvd * Z);
        hat_s[h * 16 + d] = v_s[h * 16 + d]
                          + fmaf(0.495f * fabsf(wvd), tot, lin) * invZ;
    }
    __syncthreads();

    // ======== fused projection: warp h -> cols [h*16, h*16+16) ========
    {
        float4 h4 = ((const float4*)hat_s)[lane];   // hat[lane*4 .. +3]
        float pc[16];
        #pragma unroll
        for (int i = 0; i < 16; i++) {
            const int c = h * 16 + i;
            float4 wv = *(const float4*)&w_prj[c * 128 + lane * 4];
            pc[i] = fmaf(h4.x, wv.x, fmaf(h4.y, wv.y, fmaf(h4.z, wv.z, h4.w * wv.w)));
        }
        // butterfly transpose-reduce over the 16 partial columns
        #pragma unroll
        for (int r = 0; r < 4; r++) {
            const int half = 8 >> r;
            const bool hi = (lane >> r) & 1;
            #pragma unroll
            for (int j = 0; j < 8; j++) {
                if (j < half) {
                    float send = hi ? pc[j] : pc[j + half];
                    float keep = hi ? pc[j + half] : pc[j];
                    float recv = __shfl_xor_sync(0xffffffffu, send, 1 << r);
                    pc[j] = keep + recv;
                }
            }
        }
        float cval = pc[0] + __shfl_xor_sync(0xffffffffu, pc[0], 16);
        if (lane < 16) {
            int i = ((lane & 1) << 3) | (((lane >> 1) & 1) << 2)
                  | (((lane >> 2) & 1) << 1) | ((lane >> 3) & 1);
            const int c = h * 16 + i;
            out[row * 128 + c] = cval + b_prj[c];
        }
    }
}

// ---------------------------------------------------------------------------
extern "C" void kernel_launch(void* const* d_in, const int* in_sizes, int n_in,
                              void* d_out, int out_size) {
    const float* x     = (const float*)d_in[0];
    const float* e     = (const float*)d_in[1];
    const float* w_qkv = (const float*)d_in[2];
    const float* w_ekv = (const float*)d_in[3];
    const float* b_ekv = (const float*)d_in[4];
    const float* w_prj = (const float*)d_in[5];
    const float* b_prj = (const float*)d_in[6];
    float* out = (float*)d_out;

    cudaFuncSetAttribute((const void*)qv_kernel,
                         cudaFuncAttributeMaxDynamicSharedMemorySize, QV_SMEM_BYTES);

    qv_kernel       <<<dim3(4, 32), 128, QV_SMEM_BYTES>>>(x, w_qkv);
    attn_proj_kernel<<<ROWS_,       256>>>(e, w_ekv, b_ekv, w_prj, b_prj, out);
}